// round 14
// baseline (speedup 1.0000x reference)
#include <cuda_runtime.h>
#include <cuda_fp16.h>
#include <cuda_bf16.h>
#include <cstdint>

#define ROWS_TOTAL 16384
#define DIM 2048
#define NTOT 4096

// ---------------- device scratch (static; no runtime alloc) ----------------
__device__ __align__(16) __nv_bfloat16 g_Ehi[NTOT * 64];
__device__ __align__(16) __nv_bfloat16 g_Elo[NTOT * 64];
__device__ __align__(16) __nv_bfloat16 g_Whi[64 * DIM];
__device__ __align__(16) __nv_bfloat16 g_Wlo[64 * DIM];
__device__ __align__(16) __nv_bfloat16 g_Hhi[(size_t)ROWS_TOTAL * 64];
__device__ __align__(16) __nv_bfloat16 g_Hlo[(size_t)ROWS_TOTAL * 64];
__device__ __align__(16) __half g_E[(size_t)ROWS_TOTAL * NTOT];      // exp(logit-8), 134MB
__device__ __align__(16) float g_rsum[(size_t)ROWS_TOTAL * 32];      // per-tile row sums
__device__ __align__(16) float g_part[512 * NTOT];
__device__ float g_d[4 * NTOT];

// ---------------- helpers ----------------
__device__ __forceinline__ uint32_t smem_u32(const void* p) {
    uint32_t a;
    asm("{ .reg .u64 t; cvta.to.shared.u64 t, %1; cvt.u32.u64 %0, t; }" : "=r"(a) : "l"(p));
    return a;
}
#define SW128(o) ((o) ^ (((o) >> 3) & 0x70))
#define CP_ASYNC16(dst, src) \
    asm volatile("cp.async.cg.shared.global [%0], [%1], 16;" :: "r"(dst), "l"(src))
#define CP_COMMIT() asm volatile("cp.async.commit_group;" ::: "memory")
#define CP_WAIT0()  asm volatile("cp.async.wait_group 0;" ::: "memory")

__device__ __forceinline__ void ldsm4(uint32_t addr, uint32_t& r0, uint32_t& r1,
                                      uint32_t& r2, uint32_t& r3) {
    asm volatile("ldmatrix.sync.aligned.m8n8.x4.shared.b16 {%0,%1,%2,%3}, [%4];"
                 : "=r"(r0), "=r"(r1), "=r"(r2), "=r"(r3) : "r"(addr));
}
__device__ __forceinline__ void mma_bf16(float* c, const uint32_t* a, const uint32_t* b) {
    asm volatile(
        "mma.sync.aligned.m16n8k16.row.col.f32.bf16.bf16.f32 "
        "{%0,%1,%2,%3}, {%4,%5,%6,%7}, {%8,%9}, {%0,%1,%2,%3};"
        : "+f"(c[0]), "+f"(c[1]), "+f"(c[2]), "+f"(c[3])
        : "r"(a[0]), "r"(a[1]), "r"(a[2]), "r"(a[3]), "r"(b[0]), "r"(b[1]));
}

__device__ __forceinline__ uint32_t split_pack_hi(float a, float b, uint32_t& lo) {
    __nv_bfloat162 h = __floats2bfloat162_rn(a, b);
    float ra = a - __bfloat162float(h.x);
    float rb = b - __bfloat162float(h.y);
    __nv_bfloat162 l = __floats2bfloat162_rn(ra, rb);
    lo = *reinterpret_cast<uint32_t*>(&l);
    return *reinterpret_cast<uint32_t*>(&h);
}

// ---------------- prep kernels ----------------
__global__ void k_norm_emb(const float* __restrict__ emb) {
    int n = blockIdx.x * 8 + (threadIdx.x >> 5);
    int lane = threadIdx.x & 31;
    float v0 = emb[n * 64 + lane];
    float v1 = emb[n * 64 + lane + 32];
    float ss = v0 * v0 + v1 * v1;
    #pragma unroll
    for (int o = 16; o; o >>= 1) ss += __shfl_xor_sync(0xffffffffu, ss, o);
    float inv = rsqrtf(ss);
    float e0 = v0 * inv, e1 = v1 * inv;
    __nv_bfloat16 h0 = __float2bfloat16_rn(e0);
    __nv_bfloat16 h1 = __float2bfloat16_rn(e1);
    g_Ehi[n * 64 + lane] = h0;
    g_Ehi[n * 64 + lane + 32] = h1;
    g_Elo[n * 64 + lane] = __float2bfloat16_rn(e0 - __bfloat162float(h0));
    g_Elo[n * 64 + lane + 32] = __float2bfloat16_rn(e1 - __bfloat162float(h1));
}

__global__ void k_prep_w(const float* __restrict__ W) {
    int t = blockIdx.x * 256 + threadIdx.x;   // t = k*64 + n
    if (t >= DIM * 64) return;
    int k = t >> 6, n = t & 63;
    float v = W[t];
    __nv_bfloat16 h = __float2bfloat16_rn(v);
    g_Whi[n * DIM + k] = h;
    g_Wlo[n * DIM + k] = __float2bfloat16_rn(v - __bfloat162float(h));
}

// ---------------- GEMM1: h = x @ W + b (mma.sync, split bf16, full K) ------
#define G1_SMEM 65536
__global__ void __launch_bounds__(256, 2) k_gemm1_mma(const float* __restrict__ X,
                                                      const float* __restrict__ bias) {
    extern __shared__ char smem[];
    uint32_t sb = smem_u32(smem);
    int tid = threadIdx.x, wid = tid >> 5, lane = tid & 31;
    int rowbase = blockIdx.x * 64;
    const uint32_t XHI = 0, XLO = 8192, WHI = 16384, WLO = 24576, BUF = 32768;

    float acc[4][4] = {};
    float4 xv[4];

    int warp_m = wid & 3, warp_n = wid >> 2;
    int mbase = warp_m * 16, nb0 = warp_n * 32;
    int a_row = lane & 15;
    int a_kadd = (lane >> 4) << 3;
    int b_row = ((lane >> 4) << 3) + (lane & 7);
    int b_kadd = lane & 8;

    auto cpa_w = [&](int c) {
        int kb = c * 64; int b = c & 1;
        #pragma unroll
        for (int u = 0; u < 2; u++) {
            int f = tid + u * 256;
            int n = f >> 3, cq = f & 7;
            uint32_t off = SW128((uint32_t)(n * 128 + cq * 16));
            CP_ASYNC16(sb + WHI + b * BUF + off, &g_Whi[n * DIM + kb + cq * 8]);
            CP_ASYNC16(sb + WLO + b * BUF + off, &g_Wlo[n * DIM + kb + cq * 8]);
        }
        CP_COMMIT();
    };
    auto ldg_x = [&](int c) {
        int kb = c * 64;
        #pragma unroll
        for (int u = 0; u < 4; u++) {
            int f = tid + u * 256;
            int row = f >> 4, kq = f & 15;
            xv[u] = *(const float4*)&X[(size_t)(rowbase + row) * DIM + kb + kq * 4];
        }
    };
    auto sts_x = [&](int c) {
        int b = c & 1;
        #pragma unroll
        for (int u = 0; u < 4; u++) {
            int f = tid + u * 256;
            int row = f >> 4, kq = f & 15;
            uint32_t l0, l1;
            uint32_t h0 = split_pack_hi(xv[u].x, xv[u].y, l0);
            uint32_t h1 = split_pack_hi(xv[u].z, xv[u].w, l1);
            uint32_t off = SW128((uint32_t)(row * 128 + kq * 8));
            *(uint2*)(smem + XHI + b * BUF + off) = make_uint2(h0, h1);
            *(uint2*)(smem + XLO + b * BUF + off) = make_uint2(l0, l1);
        }
    };

    cpa_w(0);
    ldg_x(0);
    sts_x(0);
    CP_WAIT0();
    __syncthreads();
    for (int c = 0; c < 32; c++) {
        if (c + 1 < 32) { cpa_w(c + 1); ldg_x(c + 1); }
        int b = c & 1;
        uint32_t xh = sb + XHI + b * BUF, xl = sb + XLO + b * BUF;
        uint32_t wh = sb + WHI + b * BUF, wl = sb + WLO + b * BUF;
        #pragma unroll
        for (int ks = 0; ks < 4; ks++) {
            int k0 = ks * 16;
            uint32_t ahi[4], alo[4];
            uint32_t aoff = SW128((uint32_t)((mbase + a_row) * 128 + (k0 + a_kadd) * 2));
            ldsm4(xh + aoff, ahi[0], ahi[1], ahi[2], ahi[3]);
            ldsm4(xl + aoff, alo[0], alo[1], alo[2], alo[3]);
            uint32_t bh[2][4], bl[2][4];
            #pragma unroll
            for (int nh = 0; nh < 2; nh++) {
                uint32_t boff = SW128((uint32_t)((nb0 + nh * 16 + b_row) * 128 + (k0 + b_kadd) * 2));
                ldsm4(wh + boff, bh[nh][0], bh[nh][1], bh[nh][2], bh[nh][3]);
                ldsm4(wl + boff, bl[nh][0], bl[nh][1], bl[nh][2], bl[nh][3]);
            }
            #pragma unroll
            for (int nh = 0; nh < 2; nh++) {
                mma_bf16(acc[nh * 2],     ahi, bh[nh]);
                mma_bf16(acc[nh * 2 + 1], ahi, bh[nh] + 2);
            }
            #pragma unroll
            for (int nh = 0; nh < 2; nh++) {
                mma_bf16(acc[nh * 2],     ahi, bl[nh]);
                mma_bf16(acc[nh * 2 + 1], ahi, bl[nh] + 2);
            }
            #pragma unroll
            for (int nh = 0; nh < 2; nh++) {
                mma_bf16(acc[nh * 2],     alo, bh[nh]);
                mma_bf16(acc[nh * 2 + 1], alo, bh[nh] + 2);
            }
        }
        if (c + 1 < 32) sts_x(c + 1);
        CP_WAIT0();
        __syncthreads();
    }

    int r0 = rowbase + mbase + (lane >> 2);
    int cb = (lane & 3) * 2;
    #pragma unroll
    for (int half = 0; half < 2; half++) {
        int row = r0 + half * 8;
        size_t ro = (size_t)row * 64;
        #pragma unroll
        for (int nt = 0; nt < 4; nt++) {
            int col = nb0 + nt * 8 + cb;
            float f0 = acc[nt][half * 2]     + bias[col];
            float f1 = acc[nt][half * 2 + 1] + bias[col + 1];
            uint32_t lo;
            uint32_t hi = split_pack_hi(f0, f1, lo);
            *(uint32_t*)&g_Hhi[ro + col] = hi;
            *(uint32_t*)&g_Hlo[ro + col] = lo;
        }
    }
}

// ------ GEMM2 fused: E = exp(H @ embn^T - 8), per-tile row sums ------------
// grid (32 n-tiles of 128, 128 row-tiles of 128). 256 threads (8 warps, 2m x 4n),
// warp tile 64x32. Epilogue: per-warp private staging (pitch 144, conflict-free
// scatter), coalesced 16B STG, no block syncs until final rsum write.
#define G2_SMEM 76800
#define WPITCH 144
__global__ void __launch_bounds__(256, 2) k_gemm2_mma() {
    extern __shared__ char smem[];
    uint32_t sb = smem_u32(smem);
    int tid = threadIdx.x, wid = tid >> 5, lane = tid & 31;
    int nbase = blockIdx.x * 128, rowbase = blockIdx.y * 128;
    const uint32_t AHI = 0, ALO = 16384, BHI = 32768, BLO = 49152, RS = 65536;
    const uint32_t WST = 67584;                    // 8 warps x 1152B private staging

    #pragma unroll
    for (int u = 0; u < 4; u++) {
        int f = tid + u * 256;                     // 0..1023
        int row = f >> 3, cq = f & 7;
        uint32_t off = SW128((uint32_t)(row * 128 + cq * 16));
        *(uint4*)(smem + AHI + off) = *(const uint4*)&g_Hhi[(size_t)(rowbase + row) * 64 + cq * 8];
        *(uint4*)(smem + ALO + off) = *(const uint4*)&g_Hlo[(size_t)(rowbase + row) * 64 + cq * 8];
    }
    #pragma unroll
    for (int u = 0; u < 4; u++) {
        int f = tid + u * 256;                     // 0..1023
        int n = f >> 3, cq = f & 7;
        uint32_t off = SW128((uint32_t)(n * 128 + cq * 16));
        *(uint4*)(smem + BHI + off) = *(const uint4*)&g_Ehi[(size_t)(nbase + n) * 64 + cq * 8];
        *(uint4*)(smem + BLO + off) = *(const uint4*)&g_Elo[(size_t)(nbase + n) * 64 + cq * 8];
    }
    __syncthreads();

    int warp_m = wid & 1, warp_n = wid >> 1;       // 2 x 4
    int mbase = warp_m * 64, nb0 = warp_n * 32;
    float acc[4][4][4] = {};                       // [mt][np*2+nh][frag]
    int a_row = lane & 15;
    int a_kadd = (lane >> 4) << 3;
    int b_row = ((lane >> 4) << 3) + (lane & 7);
    int b_kadd = lane & 8;

    #pragma unroll
    for (int ks = 0; ks < 4; ks++) {
        int k0 = ks * 16;
        uint32_t ahi[4][4], alo[4][4];
        #pragma unroll
        for (int mt = 0; mt < 4; mt++) {
            uint32_t aoff = SW128((uint32_t)((mbase + mt * 16 + a_row) * 128 + (k0 + a_kadd) * 2));
            ldsm4(sb + AHI + aoff, ahi[mt][0], ahi[mt][1], ahi[mt][2], ahi[mt][3]);
            ldsm4(sb + ALO + aoff, alo[mt][0], alo[mt][1], alo[mt][2], alo[mt][3]);
        }
        uint32_t bh[2][4], bl[2][4];
        #pragma unroll
        for (int np = 0; np < 2; np++) {
            uint32_t boff = SW128((uint32_t)((nb0 + np * 16 + b_row) * 128 + (k0 + b_kadd) * 2));
            ldsm4(sb + BHI + boff, bh[np][0], bh[np][1], bh[np][2], bh[np][3]);
            ldsm4(sb + BLO + boff, bl[np][0], bl[np][1], bl[np][2], bl[np][3]);
        }
        #pragma unroll
        for (int mt = 0; mt < 4; mt++)
            #pragma unroll
            for (int np = 0; np < 2; np++) {
                mma_bf16(acc[mt][np * 2],     ahi[mt], bh[np]);
                mma_bf16(acc[mt][np * 2 + 1], ahi[mt], bh[np] + 2);
            }
        #pragma unroll
        for (int mt = 0; mt < 4; mt++)
            #pragma unroll
            for (int np = 0; np < 2; np++) {
                mma_bf16(acc[mt][np * 2],     ahi[mt], bl[np]);
                mma_bf16(acc[mt][np * 2 + 1], ahi[mt], bl[np] + 2);
            }
        #pragma unroll
        for (int mt = 0; mt < 4; mt++)
            #pragma unroll
            for (int np = 0; np < 2; np++) {
                mma_bf16(acc[mt][np * 2],     alo[mt], bh[np]);
                mma_bf16(acc[mt][np * 2 + 1], alo[mt], bh[np] + 2);
            }
    }

    // per-warp epilogue: exp -> private stage -> coalesced STG (no block sync)
    float* rs = (float*)(smem + RS);               // [128][4]
    uint32_t wbase = WST + wid * 1152;
    int quad = lane >> 2, ql4 = (lane & 3) * 4;
    #pragma unroll
    for (int mt = 0; mt < 4; mt++) {
        #pragma unroll
        for (int half = 0; half < 2; half++) {
            int rloc = mbase + mt * 16 + half * 8 + quad;
            float rsum = 0.0f;
            #pragma unroll
            for (int j = 0; j < 4; j++) {
                float e0 = __expf(acc[mt][j][half * 2]     - 8.0f);
                float e1 = __expf(acc[mt][j][half * 2 + 1] - 8.0f);
                rsum += e0 + e1;
                __half2 p = __floats2half2_rn(e0, e1);
                *(uint32_t*)(smem + wbase + quad * WPITCH + j * 16 + ql4) =
                    *reinterpret_cast<uint32_t*>(&p);
            }
            rsum += __shfl_xor_sync(0xffffffffu, rsum, 1);
            rsum += __shfl_xor_sync(0xffffffffu, rsum, 2);
            if ((lane & 3) == 0) rs[rloc * 4 + warp_n] = rsum;
            __syncwarp();
            // coalesced store: 32 lanes = 8 rows x 4 segs of 16B (64B/row)
            int srow = lane >> 2, sseg = lane & 3;
            uint4 v = *(uint4*)(smem + wbase + srow * WPITCH + sseg * 16);
            int grow = rowbase + mbase + mt * 16 + half * 8 + srow;
            *(uint4*)&g_E[(size_t)grow * NTOT + nbase + nb0 + sseg * 8] = v;
            __syncwarp();
        }
    }
    __syncthreads();
    if (tid < 128) {
        float4 v = *(float4*)&rs[tid * 4];
        g_rsum[(size_t)(rowbase + tid) * 32 + blockIdx.x] = (v.x + v.y) + (v.z + v.w);
    }
}

// ------- accumulate d partials (inline group scales, pure streaming) --------
__global__ void k_accum(const float* __restrict__ imp) {
    int tid = threadIdx.x;
    int rb = blockIdx.x * 32;
    __shared__ float sscale[3][32];
    if (tid < 96) {
        int g = tid >> 5;
        int r = rb + (tid & 31);
        const float4* p = (const float4*)(g_rsum + (size_t)r * 32);
        float s = 0.0f;
        if (g == 0) {
            #pragma unroll
            for (int i = 0; i < 4; i++) { float4 v = p[i]; s += (v.x + v.y) + (v.z + v.w); }
        } else if (g == 1) {
            #pragma unroll
            for (int i = 4; i < 6; i++) { float4 v = p[i]; s += (v.x + v.y) + (v.z + v.w); }
        } else {
            #pragma unroll
            for (int i = 6; i < 8; i++) { float4 v = p[i]; s += (v.x + v.y) + (v.z + v.w); }
        }
        sscale[g][tid & 31] = imp[r] / s;
    }
    __syncthreads();
    int grp = (tid < 128) ? 0 : (tid < 192 ? 1 : 2);
    float acc[16] = {};
    for (int ri = 0; ri < 32; ri++) {
        int r = rb + ri;
        float sc = sscale[grp][ri];
        const uint4* lp = (const uint4*)(g_E + (size_t)r * NTOT + tid * 16);
        uint4 v0 = lp[0];
        uint4 v1 = lp[1];
        const uint32_t w[8] = {v0.x, v0.y, v0.z, v0.w, v1.x, v1.y, v1.z, v1.w};
        #pragma unroll
        for (int q = 0; q < 8; q++) {
            float2 f = __half22float2(*reinterpret_cast<const __half2*>(&w[q]));
            acc[q * 2]     = fmaf(f.x, sc, acc[q * 2]);
            acc[q * 2 + 1] = fmaf(f.y, sc, acc[q * 2 + 1]);
        }
    }
    float* pp = g_part + (size_t)blockIdx.x * NTOT + tid * 16;
    #pragma unroll
    for (int q = 0; q < 4; q++)
        *(float4*)&pp[q * 4] = make_float4(acc[q * 4], acc[q * 4 + 1],
                                           acc[q * 4 + 2], acc[q * 4 + 3]);
}

__global__ void k_reduce_part() {
    int t = blockIdx.x * 256 + threadIdx.x;
    int b = t >> 12; int n = t & 4095;
    float s = 0.0f;
    #pragma unroll 8
    for (int p = 0; p < 128; p++) s += g_part[(size_t)(b * 128 + p) * NTOT + n];
    g_d[t] = s;
}

// ---------------- top-k sparsify + output ----------------------------------
__global__ void k_topk(float* __restrict__ out) {
    int b = blockIdx.x / 3, g = blockIdx.x % 3;
    int gsize = (g == 0) ? 2048 : 1024;
    int doff = (g == 0) ? 0 : (g == 1 ? 2048 : 3072);
    int K = (g == 0) ? 8 : (g == 1 ? 4 : 6);
    __shared__ float vals[2048];
    __shared__ float rv[256];
    __shared__ int ri[256];
    __shared__ float selv[8];
    __shared__ int seli[8];
    __shared__ float ssum;
    int tid = threadIdx.x;
    for (int i = tid; i < gsize; i += 256) vals[i] = g_d[b * 4096 + doff + i];
    float* ob = out + b * 5120;
    if (g == 0)      { for (int i = tid; i < 2048; i += 256) ob[i] = 0.0f; }
    else if (g == 1) { for (int i = tid; i < 2048; i += 256) ob[2048 + i] = 0.0f; }
    else             { for (int i = tid; i < 1024; i += 256) ob[4096 + i] = 0.0f; }
    __syncthreads();

    for (int kk = 0; kk < K; kk++) {
        float bv = -1e30f; int bi = 0x7fffffff;
        for (int i = tid; i < gsize; i += 256) {
            float v = vals[i];
            if (v > bv || (v == bv && i < bi)) { bv = v; bi = i; }
        }
        rv[tid] = bv; ri[tid] = bi;
        __syncthreads();
        for (int s = 128; s; s >>= 1) {
            if (tid < s) {
                float v2 = rv[tid + s]; int i2 = ri[tid + s];
                if (v2 > rv[tid] || (v2 == rv[tid] && i2 < ri[tid])) { rv[tid] = v2; ri[tid] = i2; }
            }
            __syncthreads();
        }
        if (tid == 0) { selv[kk] = rv[0]; seli[kk] = ri[0]; vals[ri[0]] = -1e30f; }
        __syncthreads();
    }
    if (tid == 0) {
        float s = 0.0f;
        for (int kk = 0; kk < K; kk++) s += selv[kk];
        ssum = 1.0f / (s + 1e-8f);
    }
    __syncthreads();
    if (tid < K) {
        float wv = selv[tid] * ssum;
        int idx = seli[tid];
        if (g == 0) ob[idx] = wv;
        else if (g == 1) { ob[2048 + idx] = wv; ob[3072 + idx] = wv; }
        else ob[4096 + idx] = wv;
    }
}

// ---------------------------------------------------------------------------
extern "C" void kernel_launch(void* const* d_in, const int* in_sizes, int n_in,
                              void* d_out, int out_size) {
    const float *x = nullptr, *imp = nullptr, *W = nullptr, *bias = nullptr, *emb = nullptr;
    for (int i = 0; i < n_in; i++) {
        switch (in_sizes[i]) {
            case 33554432: x    = (const float*)d_in[i]; break;  // 4*4096*2048
            case 16384:    imp  = (const float*)d_in[i]; break;  // 4*4096
            case 131072:   W    = (const float*)d_in[i]; break;  // 2048*64
            case 64:       bias = (const float*)d_in[i]; break;  // 64
            case 262144:   emb  = (const float*)d_in[i]; break;  // 4096*64
            default: break;
        }
    }
    cudaFuncSetAttribute(k_gemm1_mma, cudaFuncAttributeMaxDynamicSharedMemorySize, G1_SMEM);
    cudaFuncSetAttribute(k_gemm2_mma, cudaFuncAttributeMaxDynamicSharedMemorySize, G2_SMEM);

    k_norm_emb<<<512, 256>>>(emb);                   // 0
    k_prep_w<<<512, 256>>>(W);                       // 1
    k_gemm1_mma<<<256, 256, G1_SMEM>>>(x, bias);     // 2
    k_gemm2_mma<<<dim3(32, 128), 256, G2_SMEM>>>();  // 3  <- profiled
    k_accum<<<512, 256>>>(imp);                      // 4
    k_reduce_part<<<64, 256>>>();                    // 5
    k_topk<<<12, 256>>>((float*)d_out);              // 6
}

// round 15
// speedup vs baseline: 1.0388x; 1.0388x over previous
#include <cuda_runtime.h>
#include <cuda_fp16.h>
#include <cuda_bf16.h>
#include <cstdint>

#define ROWS_TOTAL 16384
#define DIM 2048
#define NTOT 4096

// ---------------- device scratch (static; no runtime alloc) ----------------
__device__ __align__(16) __nv_bfloat16 g_Ehi[NTOT * 64];
__device__ __align__(16) __nv_bfloat16 g_Elo[NTOT * 64];
__device__ __align__(16) __nv_bfloat16 g_Whi[64 * DIM];
__device__ __align__(16) __nv_bfloat16 g_Wlo[64 * DIM];
__device__ __align__(16) __nv_bfloat16 g_Hhi[(size_t)ROWS_TOTAL * 64];
__device__ __align__(16) __nv_bfloat16 g_Hlo[(size_t)ROWS_TOTAL * 64];
__device__ __align__(16) __half g_E[(size_t)ROWS_TOTAL * NTOT];      // exp(logit-8), 134MB
__device__ __align__(16) float g_rsum[(size_t)ROWS_TOTAL * 32];      // per-tile row sums
__device__ __align__(16) float g_part[512 * NTOT];
__device__ float g_d[4 * NTOT];

// ---------------- helpers ----------------
__device__ __forceinline__ uint32_t smem_u32(const void* p) {
    uint32_t a;
    asm("{ .reg .u64 t; cvta.to.shared.u64 t, %1; cvt.u32.u64 %0, t; }" : "=r"(a) : "l"(p));
    return a;
}
#define SW128(o) ((o) ^ (((o) >> 3) & 0x70))
#define CP_ASYNC16(dst, src) \
    asm volatile("cp.async.cg.shared.global [%0], [%1], 16;" :: "r"(dst), "l"(src))
#define CP_COMMIT() asm volatile("cp.async.commit_group;" ::: "memory")
#define CP_WAIT0()  asm volatile("cp.async.wait_group 0;" ::: "memory")

__device__ __forceinline__ void ldsm4(uint32_t addr, uint32_t& r0, uint32_t& r1,
                                      uint32_t& r2, uint32_t& r3) {
    asm volatile("ldmatrix.sync.aligned.m8n8.x4.shared.b16 {%0,%1,%2,%3}, [%4];"
                 : "=r"(r0), "=r"(r1), "=r"(r2), "=r"(r3) : "r"(addr));
}
__device__ __forceinline__ void mma_bf16(float* c, const uint32_t* a, const uint32_t* b) {
    asm volatile(
        "mma.sync.aligned.m16n8k16.row.col.f32.bf16.bf16.f32 "
        "{%0,%1,%2,%3}, {%4,%5,%6,%7}, {%8,%9}, {%0,%1,%2,%3};"
        : "+f"(c[0]), "+f"(c[1]), "+f"(c[2]), "+f"(c[3])
        : "r"(a[0]), "r"(a[1]), "r"(a[2]), "r"(a[3]), "r"(b[0]), "r"(b[1]));
}

__device__ __forceinline__ uint32_t split_pack_hi(float a, float b, uint32_t& lo) {
    __nv_bfloat162 h = __floats2bfloat162_rn(a, b);
    float ra = a - __bfloat162float(h.x);
    float rb = b - __bfloat162float(h.y);
    __nv_bfloat162 l = __floats2bfloat162_rn(ra, rb);
    lo = *reinterpret_cast<uint32_t*>(&l);
    return *reinterpret_cast<uint32_t*>(&h);
}

// ---------------- prep kernels ----------------
__global__ void k_norm_emb(const float* __restrict__ emb) {
    int n = blockIdx.x * 8 + (threadIdx.x >> 5);
    int lane = threadIdx.x & 31;
    float v0 = emb[n * 64 + lane];
    float v1 = emb[n * 64 + lane + 32];
    float ss = v0 * v0 + v1 * v1;
    #pragma unroll
    for (int o = 16; o; o >>= 1) ss += __shfl_xor_sync(0xffffffffu, ss, o);
    float inv = rsqrtf(ss);
    float e0 = v0 * inv, e1 = v1 * inv;
    __nv_bfloat16 h0 = __float2bfloat16_rn(e0);
    __nv_bfloat16 h1 = __float2bfloat16_rn(e1);
    g_Ehi[n * 64 + lane] = h0;
    g_Ehi[n * 64 + lane + 32] = h1;
    g_Elo[n * 64 + lane] = __float2bfloat16_rn(e0 - __bfloat162float(h0));
    g_Elo[n * 64 + lane + 32] = __float2bfloat16_rn(e1 - __bfloat162float(h1));
}

__global__ void k_prep_w(const float* __restrict__ W) {
    int t = blockIdx.x * 256 + threadIdx.x;   // t = k*64 + n
    if (t >= DIM * 64) return;
    int k = t >> 6, n = t & 63;
    float v = W[t];
    __nv_bfloat16 h = __float2bfloat16_rn(v);
    g_Whi[n * DIM + k] = h;
    g_Wlo[n * DIM + k] = __float2bfloat16_rn(v - __bfloat162float(h));
}

// ---------------- GEMM1: h = x @ W + b (mma.sync, split bf16, full K) ------
#define G1_SMEM 65536
__global__ void __launch_bounds__(256, 2) k_gemm1_mma(const float* __restrict__ X,
                                                      const float* __restrict__ bias) {
    extern __shared__ char smem[];
    uint32_t sb = smem_u32(smem);
    int tid = threadIdx.x, wid = tid >> 5, lane = tid & 31;
    int rowbase = blockIdx.x * 64;
    const uint32_t XHI = 0, XLO = 8192, WHI = 16384, WLO = 24576, BUF = 32768;

    float acc[4][4] = {};
    float4 xv[4];

    int warp_m = wid & 3, warp_n = wid >> 2;
    int mbase = warp_m * 16, nb0 = warp_n * 32;
    int a_row = lane & 15;
    int a_kadd = (lane >> 4) << 3;
    int b_row = ((lane >> 4) << 3) + (lane & 7);
    int b_kadd = lane & 8;

    auto cpa_w = [&](int c) {
        int kb = c * 64; int b = c & 1;
        #pragma unroll
        for (int u = 0; u < 2; u++) {
            int f = tid + u * 256;
            int n = f >> 3, cq = f & 7;
            uint32_t off = SW128((uint32_t)(n * 128 + cq * 16));
            CP_ASYNC16(sb + WHI + b * BUF + off, &g_Whi[n * DIM + kb + cq * 8]);
            CP_ASYNC16(sb + WLO + b * BUF + off, &g_Wlo[n * DIM + kb + cq * 8]);
        }
        CP_COMMIT();
    };
    auto ldg_x = [&](int c) {
        int kb = c * 64;
        #pragma unroll
        for (int u = 0; u < 4; u++) {
            int f = tid + u * 256;
            int row = f >> 4, kq = f & 15;
            xv[u] = *(const float4*)&X[(size_t)(rowbase + row) * DIM + kb + kq * 4];
        }
    };
    auto sts_x = [&](int c) {
        int b = c & 1;
        #pragma unroll
        for (int u = 0; u < 4; u++) {
            int f = tid + u * 256;
            int row = f >> 4, kq = f & 15;
            uint32_t l0, l1;
            uint32_t h0 = split_pack_hi(xv[u].x, xv[u].y, l0);
            uint32_t h1 = split_pack_hi(xv[u].z, xv[u].w, l1);
            uint32_t off = SW128((uint32_t)(row * 128 + kq * 8));
            *(uint2*)(smem + XHI + b * BUF + off) = make_uint2(h0, h1);
            *(uint2*)(smem + XLO + b * BUF + off) = make_uint2(l0, l1);
        }
    };

    cpa_w(0);
    ldg_x(0);
    sts_x(0);
    CP_WAIT0();
    __syncthreads();
    for (int c = 0; c < 32; c++) {
        if (c + 1 < 32) { cpa_w(c + 1); ldg_x(c + 1); }
        int b = c & 1;
        uint32_t xh = sb + XHI + b * BUF, xl = sb + XLO + b * BUF;
        uint32_t wh = sb + WHI + b * BUF, wl = sb + WLO + b * BUF;
        #pragma unroll
        for (int ks = 0; ks < 4; ks++) {
            int k0 = ks * 16;
            uint32_t ahi[4], alo[4];
            uint32_t aoff = SW128((uint32_t)((mbase + a_row) * 128 + (k0 + a_kadd) * 2));
            ldsm4(xh + aoff, ahi[0], ahi[1], ahi[2], ahi[3]);
            ldsm4(xl + aoff, alo[0], alo[1], alo[2], alo[3]);
            uint32_t bh[2][4], bl[2][4];
            #pragma unroll
            for (int nh = 0; nh < 2; nh++) {
                uint32_t boff = SW128((uint32_t)((nb0 + nh * 16 + b_row) * 128 + (k0 + b_kadd) * 2));
                ldsm4(wh + boff, bh[nh][0], bh[nh][1], bh[nh][2], bh[nh][3]);
                ldsm4(wl + boff, bl[nh][0], bl[nh][1], bl[nh][2], bl[nh][3]);
            }
            #pragma unroll
            for (int nh = 0; nh < 2; nh++) {
                mma_bf16(acc[nh * 2],     ahi, bh[nh]);
                mma_bf16(acc[nh * 2 + 1], ahi, bh[nh] + 2);
            }
            #pragma unroll
            for (int nh = 0; nh < 2; nh++) {
                mma_bf16(acc[nh * 2],     ahi, bl[nh]);
                mma_bf16(acc[nh * 2 + 1], ahi, bl[nh] + 2);
            }
            #pragma unroll
            for (int nh = 0; nh < 2; nh++) {
                mma_bf16(acc[nh * 2],     alo, bh[nh]);
                mma_bf16(acc[nh * 2 + 1], alo, bh[nh] + 2);
            }
        }
        if (c + 1 < 32) sts_x(c + 1);
        CP_WAIT0();
        __syncthreads();
    }

    int r0 = rowbase + mbase + (lane >> 2);
    int cb = (lane & 3) * 2;
    #pragma unroll
    for (int half = 0; half < 2; half++) {
        int row = r0 + half * 8;
        size_t ro = (size_t)row * 64;
        #pragma unroll
        for (int nt = 0; nt < 4; nt++) {
            int col = nb0 + nt * 8 + cb;
            float f0 = acc[nt][half * 2]     + bias[col];
            float f1 = acc[nt][half * 2 + 1] + bias[col + 1];
            uint32_t lo;
            uint32_t hi = split_pack_hi(f0, f1, lo);
            *(uint32_t*)&g_Hhi[ro + col] = hi;
            *(uint32_t*)&g_Hlo[ro + col] = lo;
        }
    }
}

// ------ GEMM2 fused: E = exp(H @ embn^T - 8), per-tile row sums ------------
// grid (32 n-tiles of 128, 128 row-tiles of 128). 256 threads (8 warps, 2m x 4n),
// warp tile 64x32. cp.async prologue; block-staged epilogue (272B pitch,
// conflict-free) with fully-coalesced 16B STG (R13 form).
#define G2_SMEM 67584
#define EPITCH 272
__global__ void __launch_bounds__(256, 2) k_gemm2_mma() {
    extern __shared__ char smem[];
    uint32_t sb = smem_u32(smem);
    int tid = threadIdx.x, wid = tid >> 5, lane = tid & 31;
    int nbase = blockIdx.x * 128, rowbase = blockIdx.y * 128;
    const uint32_t AHI = 0, ALO = 16384, BHI = 32768, BLO = 49152, RS = 65536;
    const uint32_t EST = 0;                        // E staging reuses A+B region (34.8KB)

    // cp.async prologue: all 16 lines/thread in flight at once
    #pragma unroll
    for (int u = 0; u < 4; u++) {
        int f = tid + u * 256;                     // 0..1023
        int row = f >> 3, cq = f & 7;
        uint32_t off = SW128((uint32_t)(row * 128 + cq * 16));
        CP_ASYNC16(sb + AHI + off, &g_Hhi[(size_t)(rowbase + row) * 64 + cq * 8]);
        CP_ASYNC16(sb + ALO + off, &g_Hlo[(size_t)(rowbase + row) * 64 + cq * 8]);
    }
    #pragma unroll
    for (int u = 0; u < 4; u++) {
        int f = tid + u * 256;                     // 0..1023
        int n = f >> 3, cq = f & 7;
        uint32_t off = SW128((uint32_t)(n * 128 + cq * 16));
        CP_ASYNC16(sb + BHI + off, &g_Ehi[(size_t)(nbase + n) * 64 + cq * 8]);
        CP_ASYNC16(sb + BLO + off, &g_Elo[(size_t)(nbase + n) * 64 + cq * 8]);
    }
    CP_COMMIT();
    CP_WAIT0();
    __syncthreads();

    int warp_m = wid & 1, warp_n = wid >> 1;       // 2 x 4
    int mbase = warp_m * 64, nb0 = warp_n * 32;
    float acc[4][4][4] = {};                       // [mt][np*2+nh][frag]
    int a_row = lane & 15;
    int a_kadd = (lane >> 4) << 3;
    int b_row = ((lane >> 4) << 3) + (lane & 7);
    int b_kadd = lane & 8;

    #pragma unroll
    for (int ks = 0; ks < 4; ks++) {
        int k0 = ks * 16;
        uint32_t ahi[4][4], alo[4][4];
        #pragma unroll
        for (int mt = 0; mt < 4; mt++) {
            uint32_t aoff = SW128((uint32_t)((mbase + mt * 16 + a_row) * 128 + (k0 + a_kadd) * 2));
            ldsm4(sb + AHI + aoff, ahi[mt][0], ahi[mt][1], ahi[mt][2], ahi[mt][3]);
            ldsm4(sb + ALO + aoff, alo[mt][0], alo[mt][1], alo[mt][2], alo[mt][3]);
        }
        uint32_t bh[2][4], bl[2][4];
        #pragma unroll
        for (int np = 0; np < 2; np++) {
            uint32_t boff = SW128((uint32_t)((nb0 + np * 16 + b_row) * 128 + (k0 + b_kadd) * 2));
            ldsm4(sb + BHI + boff, bh[np][0], bh[np][1], bh[np][2], bh[np][3]);
            ldsm4(sb + BLO + boff, bl[np][0], bl[np][1], bl[np][2], bl[np][3]);
        }
        #pragma unroll
        for (int mt = 0; mt < 4; mt++)
            #pragma unroll
            for (int np = 0; np < 2; np++) {
                mma_bf16(acc[mt][np * 2],     ahi[mt], bh[np]);
                mma_bf16(acc[mt][np * 2 + 1], ahi[mt], bh[np] + 2);
            }
        #pragma unroll
        for (int mt = 0; mt < 4; mt++)
            #pragma unroll
            for (int np = 0; np < 2; np++) {
                mma_bf16(acc[mt][np * 2],     ahi[mt], bl[np]);
                mma_bf16(acc[mt][np * 2 + 1], ahi[mt], bl[np] + 2);
            }
        #pragma unroll
        for (int mt = 0; mt < 4; mt++)
            #pragma unroll
            for (int np = 0; np < 2; np++) {
                mma_bf16(acc[mt][np * 2],     alo[mt], bh[np]);
                mma_bf16(acc[mt][np * 2 + 1], alo[mt], bh[np] + 2);
            }
    }
    __syncthreads();                               // done reading A/B smem -> reuse for E staging

    // fused epilogue: E = exp(logit - 8) -> padded SMEM stage, row sums -> rs[]
    float* rs = (float*)(smem + RS);               // [128][4]
    int cb = (lane & 3) * 2;
    #pragma unroll
    for (int mt = 0; mt < 4; mt++) {
        #pragma unroll
        for (int half = 0; half < 2; half++) {
            int rloc = mbase + mt * 16 + half * 8 + (lane >> 2);
            float rsum = 0.0f;
            #pragma unroll
            for (int j = 0; j < 4; j++) {
                float e0 = __expf(acc[mt][j][half * 2]     - 8.0f);
                float e1 = __expf(acc[mt][j][half * 2 + 1] - 8.0f);
                rsum += e0 + e1;
                *(__half2*)(smem + EST + rloc * EPITCH + (nb0 + j * 8 + cb) * 2) =
                    __floats2half2_rn(e0, e1);
            }
            rsum += __shfl_xor_sync(0xffffffffu, rsum, 1);
            rsum += __shfl_xor_sync(0xffffffffu, rsum, 2);
            if ((lane & 3) == 0) rs[rloc * 4 + warp_n] = rsum;
        }
    }
    __syncthreads();
    // coalesced 16B stores: 2048 uint4 = 128 rows x 256B
    #pragma unroll
    for (int u = 0; u < 8; u++) {
        int f = tid + u * 256;
        int row = f >> 4, seg = f & 15;
        *(uint4*)&g_E[(size_t)(rowbase + row) * NTOT + nbase + seg * 8] =
            *(uint4*)(smem + EST + row * EPITCH + seg * 16);
    }
    if (tid < 128) {
        float4 v = *(float4*)&rs[tid * 4];
        g_rsum[(size_t)(rowbase + tid) * 32 + blockIdx.x] = (v.x + v.y) + (v.z + v.w);
    }
}

// ------- accumulate d partials (inline group scales, pure streaming) --------
__global__ void k_accum(const float* __restrict__ imp) {
    int tid = threadIdx.x;
    int rb = blockIdx.x * 32;
    __shared__ float sscale[3][32];
    if (tid < 96) {
        int g = tid >> 5;
        int r = rb + (tid & 31);
        const float4* p = (const float4*)(g_rsum + (size_t)r * 32);
        float s = 0.0f;
        if (g == 0) {
            #pragma unroll
            for (int i = 0; i < 4; i++) { float4 v = p[i]; s += (v.x + v.y) + (v.z + v.w); }
        } else if (g == 1) {
            #pragma unroll
            for (int i = 4; i < 6; i++) { float4 v = p[i]; s += (v.x + v.y) + (v.z + v.w); }
        } else {
            #pragma unroll
            for (int i = 6; i < 8; i++) { float4 v = p[i]; s += (v.x + v.y) + (v.z + v.w); }
        }
        sscale[g][tid & 31] = imp[r] / s;
    }
    __syncthreads();
    int grp = (tid < 128) ? 0 : (tid < 192 ? 1 : 2);
    float acc[16] = {};
    for (int ri = 0; ri < 32; ri++) {
        int r = rb + ri;
        float sc = sscale[grp][ri];
        const uint4* lp = (const uint4*)(g_E + (size_t)r * NTOT + tid * 16);
        uint4 v0 = lp[0];
        uint4 v1 = lp[1];
        const uint32_t w[8] = {v0.x, v0.y, v0.z, v0.w, v1.x, v1.y, v1.z, v1.w};
        #pragma unroll
        for (int q = 0; q < 8; q++) {
            float2 f = __half22float2(*reinterpret_cast<const __half2*>(&w[q]));
            acc[q * 2]     = fmaf(f.x, sc, acc[q * 2]);
            acc[q * 2 + 1] = fmaf(f.y, sc, acc[q * 2 + 1]);
        }
    }
    float* pp = g_part + (size_t)blockIdx.x * NTOT + tid * 16;
    #pragma unroll
    for (int q = 0; q < 4; q++)
        *(float4*)&pp[q * 4] = make_float4(acc[q * 4], acc[q * 4 + 1],
                                           acc[q * 4 + 2], acc[q * 4 + 3]);
}

__global__ void k_reduce_part() {
    int t = blockIdx.x * 256 + threadIdx.x;
    int b = t >> 12; int n = t & 4095;
    float s = 0.0f;
    #pragma unroll 8
    for (int p = 0; p < 128; p++) s += g_part[(size_t)(b * 128 + p) * NTOT + n];
    g_d[t] = s;
}

// ---------------- top-k sparsify + output ----------------------------------
__global__ void k_topk(float* __restrict__ out) {
    int b = blockIdx.x / 3, g = blockIdx.x % 3;
    int gsize = (g == 0) ? 2048 : 1024;
    int doff = (g == 0) ? 0 : (g == 1 ? 2048 : 3072);
    int K = (g == 0) ? 8 : (g == 1 ? 4 : 6);
    __shared__ float vals[2048];
    __shared__ float rv[256];
    __shared__ int ri[256];
    __shared__ float selv[8];
    __shared__ int seli[8];
    __shared__ float ssum;
    int tid = threadIdx.x;
    for (int i = tid; i < gsize; i += 256) vals[i] = g_d[b * 4096 + doff + i];
    float* ob = out + b * 5120;
    if (g == 0)      { for (int i = tid; i < 2048; i += 256) ob[i] = 0.0f; }
    else if (g == 1) { for (int i = tid; i < 2048; i += 256) ob[2048 + i] = 0.0f; }
    else             { for (int i = tid; i < 1024; i += 256) ob[4096 + i] = 0.0f; }
    __syncthreads();

    for (int kk = 0; kk < K; kk++) {
        float bv = -1e30f; int bi = 0x7fffffff;
        for (int i = tid; i < gsize; i += 256) {
            float v = vals[i];
            if (v > bv || (v == bv && i < bi)) { bv = v; bi = i; }
        }
        rv[tid] = bv; ri[tid] = bi;
        __syncthreads();
        for (int s = 128; s; s >>= 1) {
            if (tid < s) {
                float v2 = rv[tid + s]; int i2 = ri[tid + s];
                if (v2 > rv[tid] || (v2 == rv[tid] && i2 < ri[tid])) { rv[tid] = v2; ri[tid] = i2; }
            }
            __syncthreads();
        }
        if (tid == 0) { selv[kk] = rv[0]; seli[kk] = ri[0]; vals[ri[0]] = -1e30f; }
        __syncthreads();
    }
    if (tid == 0) {
        float s = 0.0f;
        for (int kk = 0; kk < K; kk++) s += selv[kk];
        ssum = 1.0f / (s + 1e-8f);
    }
    __syncthreads();
    if (tid < K) {
        float wv = selv[tid] * ssum;
        int idx = seli[tid];
        if (g == 0) ob[idx] = wv;
        else if (g == 1) { ob[2048 + idx] = wv; ob[3072 + idx] = wv; }
        else ob[4096 + idx] = wv;
    }
}

// ---------------------------------------------------------------------------
extern "C" void kernel_launch(void* const* d_in, const int* in_sizes, int n_in,
                              void* d_out, int out_size) {
    const float *x = nullptr, *imp = nullptr, *W = nullptr, *bias = nullptr, *emb = nullptr;
    for (int i = 0; i < n_in; i++) {
        switch (in_sizes[i]) {
            case 33554432: x    = (const float*)d_in[i]; break;  // 4*4096*2048
            case 16384:    imp  = (const float*)d_in[i]; break;  // 4*4096
            case 131072:   W    = (const float*)d_in[i]; break;  // 2048*64
            case 64:       bias = (const float*)d_in[i]; break;  // 64
            case 262144:   emb  = (const float*)d_in[i]; break;  // 4096*64
            default: break;
        }
    }
    cudaFuncSetAttribute(k_gemm1_mma, cudaFuncAttributeMaxDynamicSharedMemorySize, G1_SMEM);
    cudaFuncSetAttribute(k_gemm2_mma, cudaFuncAttributeMaxDynamicSharedMemorySize, G2_SMEM);

    k_norm_emb<<<512, 256>>>(emb);                   // 0
    k_prep_w<<<512, 256>>>(W);                       // 1
    k_gemm1_mma<<<256, 256, G1_SMEM>>>(x, bias);     // 2
    k_gemm2_mma<<<dim3(32, 128), 256, G2_SMEM>>>();  // 3  <- profiled
    k_accum<<<512, 256>>>(imp);                      // 4
    k_reduce_part<<<64, 256>>>();                    // 5
    k_topk<<<12, 256>>>((float*)d_out);              // 6
}